// round 4
// baseline (speedup 1.0000x reference)
#include <cuda_runtime.h>
#include <cstdint>

#define HH 512
#define WW 512
#define WORDS 16
#define SLAB 64
#define HALO 3
#define NTH 256
#define NWARPS (NTH / 32)
#define NOFF 12
#define NB 128
#define SLABS (HH / SLAB)

// zero-initialized; every use paired with a reset -> deterministic graph replays
__device__ int g_cnt[NB * NOFF * 2];     // [image][offset]{diff, n11}
__device__ unsigned g_arrive[NB];

__device__ __forceinline__ void count12(const unsigned* __restrict__ sm,
                                        int i, bool firstw, bool lastw,
                                        int row, int rl1, int rl2, int rl3,
                                        bool clip, unsigned* acc)
{
    constexpr int RS[NOFF] = {0, 1, 1, 1, 0, 2, 2, 2, 0, 3, 3, 3};
    constexpr int CS[NOFF] = {1, 1, 0, -1, 2, 2, 0, -2, 3, 3, 0, -3};

    const unsigned A = sm[i];
    #pragma unroll
    for (int o = 0; o < NOFF; ++o) {
        const int R = RS[o];
        const int C = CS[o];
        const int bi = i + R * WORDS;

        unsigned B;
        if (C > 0)       B = __funnelshift_r(sm[bi], sm[bi + 1], C);
        else if (C < 0)  B = __funnelshift_l(sm[bi - 1], sm[bi], -C);
        else             B = sm[bi];

        unsigned m = 0xffffffffu;
        if (C > 0 && lastw)  m = 0xffffffffu >> C;
        if (C < 0 && firstw) m = 0xffffffffu << (-C);
        if (clip) {
            if (R == 1 && row >= rl1) m = 0u;
            if (R == 2 && row >= rl2) m = 0u;
            if (R == 3 && row >= rl3) m = 0u;
        }
        acc[o] += (unsigned)(__popc((A ^ B) & m) << 16)
                |  (unsigned)__popc((A & B) & m);
    }
}

__global__ __launch_bounds__(NTH, 6)
void glcm_fused(const float* __restrict__ in, float* __restrict__ out)
{
    constexpr int RS[NOFF] = {0, 1, 1, 1, 0, 2, 2, 2, 0, 3, 3, 3};
    constexpr int CS[NOFF] = {1, 1, 0, -1, 2, 2, 0, -2, 3, 3, 0, -3};

    __shared__ unsigned sm[(SLAB + HALO) * WORDS + WORDS];  // + guard row
    __shared__ int s_diff[NOFF];
    __shared__ int s_n11[NOFF];
    __shared__ int s_last;

    const int tid  = threadIdx.x;
    const int lane = tid & 31;
    const int warp = tid >> 5;
    const int r0   = blockIdx.x * SLAB;
    const int b    = blockIdx.y;

    if (tid < NOFF) { s_diff[tid] = 0; s_n11[tid] = 0; }

    // ---- pack sign bits: rows [r0, r0+nload) -> bit-plane in SMEM ----------
    const int nload = min(SLAB + HALO, HH - r0);
    if (tid == 0) sm[nload * WORDS] = 0u;        // guard (masked reads only)

    const float4* img4 = reinterpret_cast<const float4*>(
        in + ((size_t)b * HH + r0) * WW);
    const int NG = nload * 4;                    // 128-float groups

    #pragma unroll 4
    for (int g = warp; g < NG; g += NWARPS) {
        float4 v = img4[g * 32 + lane];
        unsigned nib = (v.x > 0.0f ? 1u : 0u)
                     | (v.y > 0.0f ? 2u : 0u)
                     | (v.z > 0.0f ? 4u : 0u)
                     | (v.w > 0.0f ? 8u : 0u);
        unsigned pack = nib << ((lane & 7) * 4);
        pack |= __shfl_xor_sync(0xffffffffu, pack, 1);
        pack |= __shfl_xor_sync(0xffffffffu, pack, 2);
        pack |= __shfl_xor_sync(0xffffffffu, pack, 4);
        if ((lane & 7) == 0) sm[g * 4 + (lane >> 3)] = pack;
    }
    __syncthreads();

    // ---- fused single pass: all 12 offsets per word ------------------------
    unsigned acc[NOFF];
    #pragma unroll
    for (int o = 0; o < NOFF; ++o) acc[o] = 0;

    const bool fullslab = (r0 + SLAB + HALO <= HH);
    const int rl1 = min(SLAB, HH - 1 - r0);
    const int rl2 = min(SLAB, HH - 2 - r0);
    const int rl3 = min(SLAB, HH - 3 - r0);

    if (fullslab) {
        #pragma unroll 2
        for (int i = tid; i < SLAB * WORDS; i += NTH) {
            const int w = i & (WORDS - 1);
            count12(sm, i, w == 0, w == WORDS - 1, 0, 0, 0, 0, false, acc);
        }
    } else {
        #pragma unroll 2
        for (int i = tid; i < SLAB * WORDS; i += NTH) {
            const int w = i & (WORDS - 1);
            count12(sm, i, w == 0, w == WORDS - 1, i >> 4, rl1, rl2, rl3, true, acc);
        }
    }

    #pragma unroll
    for (int o = 0; o < NOFF; ++o) {
        unsigned v = __reduce_add_sync(0xffffffffu, acc[o]);
        if (lane == 0) {
            atomicAdd(&s_diff[o], (int)(v >> 16));
            atomicAdd(&s_n11[o],  (int)(v & 0xffffu));
        }
    }
    __syncthreads();

    if (tid < NOFF) {
        atomicAdd(&g_cnt[(b * NOFF + tid) * 2 + 0], s_diff[tid]);
        atomicAdd(&g_cnt[(b * NOFF + tid) * 2 + 1], s_n11[tid]);
    }

    // ---- last slab-block of this image finalizes ---------------------------
    if (tid == 0) {
        __threadfence();
        unsigned t = atomicAdd(&g_arrive[b], 1u);
        s_last = (t == SLABS - 1);
    }
    __syncthreads();

    if (s_last && tid < NOFF) {
        const int idx  = b * NOFF + tid;
        const int diff = atomicExch(&g_cnt[idx * 2 + 0], 0);   // read + reset
        const int n11  = atomicExch(&g_cnt[idx * 2 + 1], 0);
        if (tid == 0) atomicExch(&g_arrive[b], 0u);

        const int R  = RS[tid];
        const int Ca = CS[tid] < 0 ? -CS[tid] : CS[tid];
        const int N  = (HH - R) * (WW - Ca);
        const int n00 = N - n11 - diff;

        const float inv = 1.0f / (float)(2 * N - 4 * n00);
        float* o = out + (size_t)b * (NOFF * 4) + tid * 4;
        o[0] = (float)(4 * n00) * inv;
        const float v1 = (float)(2 * diff - 4 * n00) * inv;
        o[1] = v1;
        o[2] = v1;
        o[3] = (float)(2 * (N - 2 * diff)) * inv;
    }
}

extern "C" void kernel_launch(void* const* d_in, const int* in_sizes, int n_in,
                              void* d_out, int out_size)
{
    (void)n_in; (void)out_size; (void)in_sizes;
    dim3 grid(SLABS, NB);                        // 8 x 128 = 1024 blocks
    glcm_fused<<<grid, NTH>>>((const float*)d_in[0], (float*)d_out);
}

// round 5
// speedup vs baseline: 1.0940x; 1.0940x over previous
#include <cuda_runtime.h>
#include <cstdint>

#define HH 512
#define WW 512
#define WORDS 16
#define SLAB 128
#define HALO 3
#define NTH 512
#define NWARPS (NTH / 32)
#define NOFF 12
#define NB 128
#define SLABS (HH / SLAB)

// zero-initialized; every use paired with a reset -> deterministic graph replays
__device__ int g_cnt[NB * NOFF * 2];     // [image][offset]{diff, n11}
__device__ unsigned g_arrive[NB];

__global__ __launch_bounds__(NTH, 4)
void glcm_fused(const float* __restrict__ in, float* __restrict__ out)
{
    constexpr int RS[NOFF] = {0, 1, 1, 1, 0, 2, 2, 2, 0, 3, 3, 3};
    constexpr int CS[NOFF] = {1, 1, 0, -1, 2, 2, 0, -2, 3, 3, 0, -3};

    __shared__ unsigned sm[(SLAB + HALO) * WORDS + WORDS];  // + guard row
    __shared__ int s_diff[NOFF];
    __shared__ int s_n11[NOFF];
    __shared__ int s_last;

    const int tid  = threadIdx.x;
    const int lane = tid & 31;
    const int warp = tid >> 5;
    const int r0   = blockIdx.x * SLAB;
    const int b    = blockIdx.y;

    if (tid < NOFF) { s_diff[tid] = 0; s_n11[tid] = 0; }

    // ---- ballot pack: rows [r0, r0+nload) -> bit-plane in SMEM -------------
    // col = g*128 + c*32 + lane; ballot(v>0) yields one 32-col word directly.
    const int nload = min(SLAB + HALO, HH - r0);
    if (tid == 0) sm[nload * WORDS] = 0u;        // guard (masked reads only)

    const float* p = in + ((size_t)b * HH + r0) * WW;
    const int NG = nload * 4;                    // 128-col groups

    #pragma unroll 4
    for (int g = warp; g < NG; g += NWARPS) {
        const float* q = p + g * 128 + lane;
        float v0 = q[0];
        float v1 = q[32];
        float v2 = q[64];
        float v3 = q[96];
        unsigned b0 = __ballot_sync(0xffffffffu, v0 > 0.0f);
        unsigned b1 = __ballot_sync(0xffffffffu, v1 > 0.0f);
        unsigned b2 = __ballot_sync(0xffffffffu, v2 > 0.0f);
        unsigned b3 = __ballot_sync(0xffffffffu, v3 > 0.0f);
        if (lane == 0)
            *reinterpret_cast<uint4*>(&sm[g * 4]) = make_uint4(b0, b1, b2, b3);
    }
    __syncthreads();

    // ---- 12 separate popcount passes (low reg pressure, proven fastest) ----
    #pragma unroll
    for (int off = 0; off < NOFF; ++off) {
        const int R = RS[off];
        const int C = CS[off];
        const int nrows = min(SLAB, HH - R - r0);   // a-rows owned by this slab
        const int total = nrows * WORDS;

        unsigned diff = 0, n11 = 0;
        for (int i = tid; i < total; i += NTH) {
            const int w = i & (WORDS - 1);
            const unsigned A = sm[i];
            const int bi = i + R * WORDS;
            unsigned B;
            if (C > 0)       B = __funnelshift_r(sm[bi], sm[bi + 1], C);
            else if (C < 0)  B = __funnelshift_l(sm[bi - 1], sm[bi], -C);
            else             B = sm[bi];

            unsigned m = 0xffffffffu;
            if (C > 0 && w == WORDS - 1) m = 0xffffffffu >> C;
            if (C < 0 && w == 0)         m = 0xffffffffu << (-C);

            diff += __popc((A ^ B) & m);
            n11  += __popc((A & B) & m);
        }
        diff = __reduce_add_sync(0xffffffffu, diff);
        n11  = __reduce_add_sync(0xffffffffu, n11);
        if (lane == 0) {
            atomicAdd(&s_diff[off], (int)diff);
            atomicAdd(&s_n11[off], (int)n11);
        }
    }
    __syncthreads();

    if (tid < NOFF) {
        atomicAdd(&g_cnt[(b * NOFF + tid) * 2 + 0], s_diff[tid]);
        atomicAdd(&g_cnt[(b * NOFF + tid) * 2 + 1], s_n11[tid]);
    }

    // ---- last slab-block of this image finalizes ---------------------------
    if (tid == 0) {
        __threadfence();
        unsigned t = atomicAdd(&g_arrive[b], 1u);
        s_last = (t == SLABS - 1);
    }
    __syncthreads();

    if (s_last && tid < NOFF) {
        const int idx  = b * NOFF + tid;
        const int diff = atomicExch(&g_cnt[idx * 2 + 0], 0);   // read + reset
        const int n11  = atomicExch(&g_cnt[idx * 2 + 1], 0);
        if (tid == 0) atomicExch(&g_arrive[b], 0u);

        const int R  = RS[tid];
        const int Ca = CS[tid] < 0 ? -CS[tid] : CS[tid];
        const int N  = (HH - R) * (WW - Ca);
        const int n00 = N - n11 - diff;

        const float inv = 1.0f / (float)(2 * N - 4 * n00);
        float* o = out + (size_t)b * (NOFF * 4) + tid * 4;
        o[0] = (float)(4 * n00) * inv;
        const float v1 = (float)(2 * diff - 4 * n00) * inv;
        o[1] = v1;
        o[2] = v1;
        o[3] = (float)(2 * (N - 2 * diff)) * inv;
    }
}

extern "C" void kernel_launch(void* const* d_in, const int* in_sizes, int n_in,
                              void* d_out, int out_size)
{
    (void)n_in; (void)out_size; (void)in_sizes;
    dim3 grid(SLABS, NB);                        // 4 x 128 = 512 blocks
    glcm_fused<<<grid, NTH>>>((const float*)d_in[0], (float*)d_out);
}